// round 9
// baseline (speedup 1.0000x reference)
#include <cuda_runtime.h>
#include <stdint.h>

#define IMG_H 1024
#define IMG_W 1280
#define NPIX (IMG_H * IMG_W)
#define NPTS 4194304

// Z-buffer: key = (z_bits << 32) | point_index. Lexicographic min ==
// (min z, then min index) == reference's stable-argsort winner.
__device__ unsigned long long g_zbuf[NPIX];

// ---------- bulk-async helpers (1D cp.async.bulk, no tensormap) ----------
__device__ __forceinline__ unsigned smem_u32(const void* p) {
    return (unsigned)__cvta_generic_to_shared(p);
}
__device__ __forceinline__ void mbar_init(unsigned mb, unsigned cnt) {
    asm volatile("mbarrier.init.shared.b64 [%0], %1;" :: "r"(mb), "r"(cnt) : "memory");
}
__device__ __forceinline__ void mbar_expect_tx(unsigned mb, unsigned bytes) {
    asm volatile("mbarrier.arrive.expect_tx.shared.b64 _, [%0], %1;"
                 :: "r"(mb), "r"(bytes) : "memory");
}
__device__ __forceinline__ void mbar_wait(unsigned mb, unsigned parity) {
    asm volatile(
        "{\n\t"
        ".reg .pred P;\n\t"
        "WL_%=:\n\t"
        "mbarrier.try_wait.parity.shared.b64 P, [%0], %1;\n\t"
        "@P bra WD_%=;\n\t"
        "bra WL_%=;\n\t"
        "WD_%=:\n\t"
        "}" :: "r"(mb), "r"(parity) : "memory");
}
__device__ __forceinline__ void bulk_g2s(unsigned dst_smem, const void* src_gmem,
                                         unsigned bytes, unsigned mb) {
    asm volatile(
        "cp.async.bulk.shared::cta.global.mbarrier::complete_tx::bytes [%0], [%1], %2, [%3];"
        :: "r"(dst_smem), "l"(src_gmem), "r"(bytes), "r"(mb) : "memory");
}
__device__ __forceinline__ void bulk_s2g(void* dst_gmem, unsigned src_smem, unsigned bytes) {
    asm volatile("fence.proxy.async.shared::cta;" ::: "memory");
    asm volatile("cp.async.bulk.global.shared::cta.bulk_group [%0], [%1], %2;"
                 :: "l"(dst_gmem), "r"(src_smem), "r"(bytes) : "memory");
    asm volatile("cp.async.bulk.commit_group;" ::: "memory");
    asm volatile("cp.async.bulk.wait_group 0;" ::: "memory");
}

// Guarded fast projection (bit-exact vs reference; validated rel_err=0.0):
// fast rcp path; if u/v lands within 0.498 of a half-integer boundary
// (6x the max 3.3e-4 rcp-path error), redo with exact IEEE divides.
__device__ __forceinline__ void splat_point(float x, float y, float z,
                                            unsigned int idx,
                                            float fx, float fy, float cx, float cy) {
    if (z > 0.0f) {
        float mu = __fmul_rn(fx, x);
        float mv = __fmul_rn(fy, y);
        float rz = __frcp_rn(z);
        float uf = __fadd_rn(__fmul_rn(mu, rz), cx);
        float vf = __fadd_rn(__fmul_rn(mv, rz), cy);
        float ur = rintf(uf);
        float vr = rintf(vf);
        if (fabsf(__fadd_rn(uf, -ur)) >= 0.498f ||
            fabsf(__fadd_rn(vf, -vr)) >= 0.498f) {
            uf = __fadd_rn(__fdiv_rn(mu, z), cx);
            vf = __fadd_rn(__fdiv_rn(mv, z), cy);
            ur = rintf(uf);
            vr = rintf(vf);
        }
        int u = (int)ur;
        int v = (int)vr;
        if ((unsigned)u < (unsigned)IMG_W && (unsigned)v < (unsigned)IMG_H) {
            unsigned long long key =
                ((unsigned long long)__float_as_uint(z) << 32) | (unsigned long long)idx;
            atomicMin(&g_zbuf[v * IMG_W + u], key);  // return ignored -> RED
        }
    }
}

// 2048 points per CTA; points streamed in via ONE 24KB bulk copy (no per-lane
// LDG). The only LSU ops left are the REDs -> LSU floor ~14us instead of 25.
__global__ __launch_bounds__(256) void project_kernel(const float* __restrict__ points,
                                                      const float* __restrict__ Kmat) {
    __shared__ __align__(128) float s_pts[2048 * 3];           // 24576 B
    __shared__ __align__(8) unsigned long long s_mbar;

    int t = threadIdx.x;
    unsigned mb = smem_u32(&s_mbar);
    if (t == 0) mbar_init(mb, 1);
    __syncthreads();
    if (t == 0) {
        mbar_expect_tx(mb, 24576);
        bulk_g2s(smem_u32(s_pts),
                 (const char*)points + (size_t)blockIdx.x * 24576u, 24576, mb);
    }
    mbar_wait(mb, 0);

    float fx = Kmat[0], cx = Kmat[2], fy = Kmat[4], cy = Kmat[5];

    const float4* sp = reinterpret_cast<const float4*>(s_pts);
    float4 a = sp[t * 6 + 0];
    float4 b = sp[t * 6 + 1];
    float4 c = sp[t * 6 + 2];
    float4 d = sp[t * 6 + 3];
    float4 e = sp[t * 6 + 4];
    float4 f = sp[t * 6 + 5];

    unsigned int base = (unsigned int)(blockIdx.x * 2048 + t * 8);
    splat_point(a.x, a.y, a.z, base + 0, fx, fy, cx, cy);
    splat_point(a.w, b.x, b.y, base + 1, fx, fy, cx, cy);
    splat_point(b.z, b.w, c.x, base + 2, fx, fy, cx, cy);
    splat_point(c.y, c.z, c.w, base + 3, fx, fy, cx, cy);
    splat_point(d.x, d.y, d.z, base + 4, fx, fy, cx, cy);
    splat_point(d.w, e.x, e.y, base + 5, fx, fy, cx, cy);
    splat_point(e.z, e.w, f.x, base + 6, fx, fy, cx, cy);
    splat_point(f.y, f.z, f.w, base + 7, fx, fy, cx, cy);
}

// Fetch color[idx] (3 floats at idx*3) with two LDG.64s via the parity trick:
// base = (idx*3) & ~1 is 8B-aligned; float2 loads [base],[base+2] cover all
// three components for either parity. (Never overreads past end: last idx has
// idx*3 odd.)
__device__ __forceinline__ void fetch_color(unsigned int lo,
                                            const float* __restrict__ colors,
                                            float& r, float& g, float& b) {
    r = 0.0f; g = 0.0f; b = 0.0f;
    if (lo != 0xFFFFFFFFu) {            // idx < 2^22, sentinel low word = ~0
        unsigned int e = lo * 3u;
        unsigned int base = e & ~1u;
        const float2* cp = reinterpret_cast<const float2*>(colors + base);
        float2 a0 = __ldg(&cp[0]);
        float2 a1 = __ldg(&cp[1]);
        bool odd = (e & 1u) != 0u;
        r = odd ? a0.y : a0.x;
        g = odd ? a1.x : a0.y;
        b = odd ? a1.y : a1.x;
    }
}

// 1024 pixels per CTA. Keys arrive via one 8KB bulk load; output staged in
// smem and written via one 12KB bulk store. LSU ops per 4 px: 8 color LDGs
// only (was 13 incl. key loads + STGs).
__global__ __launch_bounds__(256) void gather_kernel(const float* __restrict__ colors,
                                                     float* __restrict__ out) {
    __shared__ __align__(128) unsigned long long s_keys[1024]; // 8192 B
    __shared__ __align__(128) float s_out[1024 * 3];           // 12288 B
    __shared__ __align__(8) unsigned long long s_mbar;

    int t = threadIdx.x;
    unsigned mb = smem_u32(&s_mbar);
    if (t == 0) mbar_init(mb, 1);
    __syncthreads();
    if (t == 0) {
        mbar_expect_tx(mb, 8192);
        bulk_g2s(smem_u32(s_keys), &g_zbuf[blockIdx.x * 1024], 8192, mb);
    }
    mbar_wait(mb, 0);

    // 4 keys per thread; only low words (index / sentinel) needed.
    const uint4* kb = reinterpret_cast<const uint4*>(s_keys);
    uint4 q0 = kb[t * 2 + 0];
    uint4 q1 = kb[t * 2 + 1];

    float c[12];
    fetch_color(q0.x, colors, c[0], c[1], c[2]);
    fetch_color(q0.z, colors, c[3], c[4], c[5]);
    fetch_color(q1.x, colors, c[6], c[7], c[8]);
    fetch_color(q1.z, colors, c[9], c[10], c[11]);

    float4* so = reinterpret_cast<float4*>(s_out);  // 48B/thread, conflict-free
    so[t * 3 + 0] = make_float4(c[0], c[1], c[2], c[3]);
    so[t * 3 + 1] = make_float4(c[4], c[5], c[6], c[7]);
    so[t * 3 + 2] = make_float4(c[8], c[9], c[10], c[11]);
    __syncthreads();

    if (t == 0) {
        bulk_s2g((char*)out + (size_t)blockIdx.x * 12288u, smem_u32(s_out), 12288);
    }
}

extern "C" void kernel_launch(void* const* d_in, const int* in_sizes, int n_in,
                              void* d_out, int out_size) {
    const float* points = (const float*)d_in[0];
    const float* colors = (const float*)d_in[1];
    const float* Kmat   = (const float*)d_in[2];
    float* out = (float*)d_out;

    // Reset z-buffer to all-ones sentinel via a memset node.
    void* zbuf_ptr = nullptr;
    cudaGetSymbolAddress(&zbuf_ptr, g_zbuf);
    cudaMemsetAsync(zbuf_ptr, 0xFF, NPIX * sizeof(unsigned long long));

    project_kernel<<<NPTS / 2048, 256>>>(points, Kmat);   // 2048 CTAs
    gather_kernel<<<NPIX / 1024, 256>>>(colors, out);     // 1280 CTAs
}